// round 8
// baseline (speedup 1.0000x reference)
#include <cuda_runtime.h>
#include <float.h>

// ---------------------------------------------------------------------------
// FeatPropagation via uniform-grid EXACT k=3 NN + inverse-distance interp.
//
// R8: knn_cell uses block-cooperative PROGRESSIVE SHELLS. R7's per-thread
// fallback ring walk (5% of queries, sparse region) was a divergent
// latency-chained pointer chase; now the whole block stages shell r=2,3,...
// into SMEM cooperatively until every query in the cell is provably done
// (__syncthreads_count vote). Also: results stored by sorted query slot and
// interp walks sorted order -> L1 catches the ~48x feature-row reuse.
//
// Ranking stays BIT-EXACT vs the JAX reference (GEMM-form d2 with explicit
// rounding intrinsics); (d2, index) lexicographic insert == top_k
// lowest-index tie-break, independent of scatter order. Stop bound is
// conservative (MARGIN >> reference rounding error) -> exact result.
// ---------------------------------------------------------------------------

#define G      16
#define G3     (G * G * G)
#define GLO    (-4.0f)
#define HV     0.5f
#define INVH   2.0f
#define MAXB   8
#define MARGIN 2e-4f

// point grid
__device__ int    g_cnt[MAXB * G3];
__device__ int    g_start[MAXB * (G3 + 1)];
__device__ int    g_cur[MAXB * G3];
__device__ float4 g_pts[1 << 15];      // sorted points {x,y,z,s2}
__device__ int    g_pid[1 << 15];      // sorted slot -> original global index
// query grid
__device__ int    g_qcnt[MAXB * G3];
__device__ int    g_qstart[MAXB * (G3 + 1)];
__device__ int    g_qcur[MAXB * G3];
__device__ float4 g_qpts[1 << 17];     // sorted queries {x,y,z,q2}
__device__ int    g_qid[1 << 17];      // sorted slot -> original global index

#define CAPQ (3 * (1 << 17))
__device__ int   g_idx[CAPQ];          // by SORTED slot
__device__ float g_w[CAPQ];            // by SORTED slot

__device__ __forceinline__ int cell1(float v) {
    int c = (int)floorf((v - GLO) * INVH);
    return min(max(c, 0), G - 1);
}

__global__ void zero_kernel(int cells) {
    int i = blockIdx.x * blockDim.x + threadIdx.x;
    if (i < cells) { g_cnt[i] = 0; g_qcnt[i] = 0; }
}

template <bool QRY>
__global__ void count_kernel(const float* __restrict__ src, int P, int total) {
    int i = blockIdx.x * blockDim.x + threadIdx.x;
    if (i >= total) return;
    int b = i / P;
    float x = src[3 * i], y = src[3 * i + 1], z = src[3 * i + 2];
    int c = (cell1(z) * G + cell1(y)) * G + cell1(x);
    atomicAdd((QRY ? g_qcnt : g_cnt) + b * G3 + c, 1);
}

// grid (B, 2): y==0 point counters, y==1 query counters. 4 cells/thread.
__global__ void __launch_bounds__(1024) scan_kernel() {
    const int b = blockIdx.x;
    int* cnt   = (blockIdx.y ? g_qcnt   : g_cnt)   + b * G3;
    int* start = (blockIdx.y ? g_qstart : g_start) + b * (G3 + 1);
    int* cur   = (blockIdx.y ? g_qcur   : g_cur)   + b * G3;

    const int tid = threadIdx.x;
    __shared__ int sm[1024];

    const int lo = tid * 4;
    int c0 = cnt[lo], c1 = cnt[lo + 1], c2 = cnt[lo + 2], c3 = cnt[lo + 3];
    const int sum = c0 + c1 + c2 + c3;
    sm[tid] = sum;
    __syncthreads();
    for (int off = 1; off < 1024; off <<= 1) {            // Hillis-Steele
        int v = (tid >= off) ? sm[tid - off] : 0;
        __syncthreads();
        sm[tid] += v;
        __syncthreads();
    }
    int run = sm[tid] - sum;
    start[lo]     = run;  cur[lo]     = run;  run += c0;
    start[lo + 1] = run;  cur[lo + 1] = run;  run += c1;
    start[lo + 2] = run;  cur[lo + 2] = run;  run += c2;
    start[lo + 3] = run;  cur[lo + 3] = run;
    if (tid == 1023) start[G3] = sm[1023];
}

template <bool QRY>
__global__ void scatter_kernel(const float* __restrict__ src, int P, int total) {
    int i = blockIdx.x * blockDim.x + threadIdx.x;
    if (i >= total) return;
    int b = i / P;
    float x = src[3 * i], y = src[3 * i + 1], z = src[3 * i + 2];
    int c = (cell1(z) * G + cell1(y)) * G + cell1(x);
    int pos = atomicAdd((QRY ? g_qcur : g_cur) + b * G3 + c, 1);
    float s2 = __fadd_rn(__fadd_rn(__fmul_rn(x, x), __fmul_rn(y, y)),
                         __fmul_rn(z, z));
    if (QRY) { g_qpts[b * P + pos] = make_float4(x, y, z, s2);
               g_qid [b * P + pos] = i; }
    else     { g_pts [b * P + pos] = make_float4(x, y, z, s2);
               g_pid [b * P + pos] = i; }
}

// ---------------------------------------------------------------------------
// knn_cell: one block per (cell, batch). Progressive shell staging in SMEM.
//   rr=1 stages the full 3x3x3 box; rr>=2 stages the Chebyshev-rr shell.
//   Block-wide vote decides whether another shell is needed.
// ---------------------------------------------------------------------------
#define KNN_T   128
#define CAP_C   1280
#define MAXRNG  (2 * 31 * 31)          // 2 slots per (dz,dy) row, rr <= 15

__global__ void __launch_bounds__(KNN_T)
knn_cell(int N, int M)
{
    const int b  = blockIdx.y;
    const int c  = blockIdx.x;
    const int bs = b * (G3 + 1);
    const int qs = g_qstart[bs + c];
    const int qe = g_qstart[bs + c + 1];
    if (qs == qe) return;                 // uniform early exit

    const int cz = c / (G * G);
    const int cy = (c / G) % G;
    const int cx = c % G;

    const int pbase = b * N;
    const int qbase = b * M;
    const int tid   = threadIdx.x;

    __shared__ int2   rng[MAXRNG];
    __shared__ float4 spts[CAP_C];
    __shared__ int    sid[CAP_C];

    for (int q0 = qs; q0 < qe; q0 += KNN_T) {
        const int  qslot = qbase + q0 + tid;     // global SORTED slot
        const bool act   = (q0 + tid) < qe;

        float qx = 0.f, qy = 0.f, qz = 0.f, q2 = 0.f;
        if (act) {
            const float4 Q = g_qpts[qslot];
            qx = Q.x; qy = Q.y; qz = Q.z; q2 = Q.w;
        }

        float d0 = 1e30f, d1 = 1e30f, d2v = 1e30f;
        int   i0 = -1,    i1 = -1,    i2 = -1;
        bool  done = !act;

        auto ins = [&](float dd, int id) {
            if (dd < d2v || (dd == d2v && id < i2)) {
                if (dd < d1 || (dd == d1 && id < i1)) {
                    d2v = d1; i2 = i1;
                    if (dd < d0 || (dd == d0 && id < i0)) {
                        d1 = d0; i1 = i0; d0 = dd; i0 = id;
                    } else { d1 = dd; i1 = id; }
                } else { d2v = dd; i2 = id; }
            }
        };
        auto dist2 = [&](const float4& P) -> float {
            const float cross = __fmaf_rn(qz, P.z,
                                  __fmaf_rn(qy, P.y, __fmul_rn(qx, P.x)));
            return __fmaf_rn(-2.0f, cross, __fadd_rn(q2, P.w));
        };

        for (int rr = 1; ; rr++) {
            // ---- cooperative range build: rr==1 -> box rows; rr>=2 -> shell
            const int W   = 2 * rr + 1;
            const int nsl = W * W;
            for (int t = tid; t < nsl; t += KNN_T) {
                const int dz = t / W - rr, dy = t % W - rr;
                const int z = cz + dz, y = cy + dy;
                int s0 = 0, e0 = 0, s1 = 0, e1 = 0;
                if (z >= 0 && z < G && y >= 0 && y < G) {
                    const int row  = (z * G + y) * G;
                    const bool full = (rr == 1) || (dz == -rr) || (dz == rr)
                                                || (dy == -rr) || (dy == rr);
                    if (full) {
                        const int xlo = max(cx - rr, 0);
                        const int xhi = min(cx + rr, G - 1);
                        s0 = g_start[bs + row + xlo];
                        e0 = g_start[bs + row + xhi + 1];
                    } else {
                        if (cx - rr >= 0) {
                            s0 = g_start[bs + row + cx - rr];
                            e0 = g_start[bs + row + cx - rr + 1];
                        }
                        if (cx + rr <= G - 1) {
                            s1 = g_start[bs + row + cx + rr];
                            e1 = g_start[bs + row + cx + rr + 1];
                        }
                    }
                }
                rng[2 * t]     = make_int2(s0, e0);
                rng[2 * t + 1] = make_int2(s1, e1);
            }
            __syncthreads();

            // ---- chunked fill + scan over the 2*nsl range slots -----------
            const int nslots2 = 2 * nsl;
            int slot = 0;
            int pos  = rng[0].x;
            while (slot < nslots2) {
                int filled = 0;
                while (slot < nslots2 && filled < CAP_C) {
                    const int2 R  = rng[slot];
                    const int  p0 = max(pos, R.x);
                    const int  avail = R.y - p0;
                    if (avail <= 0) {
                        slot++;
                        if (slot < nslots2) pos = rng[slot].x;
                        continue;
                    }
                    const int take = min(avail, CAP_C - filled);
                    for (int i = tid; i < take; i += KNN_T) {
                        spts[filled + i] = g_pts[pbase + p0 + i];
                        sid [filled + i] = g_pid[pbase + p0 + i];
                    }
                    filled += take;
                    pos = p0 + take;
                    if (pos >= R.y) {
                        slot++;
                        if (slot < nslots2) pos = rng[slot].x;
                    }
                }
                __syncthreads();

                if (!done) {
                    const int k4 = filled & ~3;
                    for (int j = 0; j < k4; j += 4) {
                        const float dd0 = dist2(spts[j + 0]);
                        const float dd1 = dist2(spts[j + 1]);
                        const float dd2 = dist2(spts[j + 2]);
                        const float dd3 = dist2(spts[j + 3]);
                        const float gm  = fminf(fminf(dd0, dd1),
                                                fminf(dd2, dd3));
                        if (gm <= d2v) {        // '<=' keeps tie-break exact
                            ins(dd0, sid[j + 0]);
                            ins(dd1, sid[j + 1]);
                            ins(dd2, sid[j + 2]);
                            ins(dd3, sid[j + 3]);
                        }
                    }
                    for (int j = k4; j < filled; j++)
                        ins(dist2(spts[j]), sid[j]);
                }
                __syncthreads();
            }

            // ---- stop check at box radius rr ------------------------------
            if (!done) {
                const float fxl = (cx - rr <= 0)     ? 1e30f : qx - (GLO + (cx - rr) * HV);
                const float fxh = (cx + rr >= G - 1) ? 1e30f : (GLO + (cx + rr + 1) * HV) - qx;
                const float fyl = (cy - rr <= 0)     ? 1e30f : qy - (GLO + (cy - rr) * HV);
                const float fyh = (cy + rr >= G - 1) ? 1e30f : (GLO + (cy + rr + 1) * HV) - qy;
                const float fzl = (cz - rr <= 0)     ? 1e30f : qz - (GLO + (cz - rr) * HV);
                const float fzh = (cz + rr >= G - 1) ? 1e30f : (GLO + (cz + rr + 1) * HV) - qz;
                const float lb  = fminf(fminf(fminf(fxl, fxh), fminf(fyl, fyh)),
                                        fminf(fzl, fzh));
                if (lb >= 1e29f) done = true;   // whole grid covered
                else if (i2 >= 0 && lb > 0.0f && d2v + MARGIN <= lb * lb)
                    done = true;
            }
            if (__syncthreads_count(done ? 0 : 1) == 0) break;
        }

        if (act) {
            const float e0 = sqrtf(fmaxf(d0,  1e-12f));
            const float e1 = sqrtf(fmaxf(d1,  1e-12f));
            const float e2 = sqrtf(fmaxf(d2v, 1e-12f));
            const float r0 = __fdiv_rn(1.0f, __fadd_rn(e0, 1e-8f));
            const float r1 = __fdiv_rn(1.0f, __fadd_rn(e1, 1e-8f));
            const float r2 = __fdiv_rn(1.0f, __fadd_rn(e2, 1e-8f));
            const float s  = __fadd_rn(__fadd_rn(r0, r1), r2);

            const int base  = 3 * qslot;       // by SORTED slot
            g_idx[base + 0] = i0;
            g_idx[base + 1] = i1;
            g_idx[base + 2] = i2;
            g_w[base + 0]   = __fdiv_rn(r0, s);
            g_w[base + 1]   = __fdiv_rn(r1, s);
            g_w[base + 2]   = __fdiv_rn(r2, s);
        }
    }
}

// interp walks SORTED order (spatial locality -> feature-row reuse in L1);
// output row comes from g_qid.
__global__ void __launch_bounds__(256)
interp_kernel(const float* __restrict__ feat, float* __restrict__ out,
              int C4, int total)
{
    const int t = blockIdx.x * 256 + threadIdx.x;
    if (t >= total) return;

    const int j  = t / C4;                 // sorted query slot
    const int cg = t - j * C4;

    const int   base = 3 * j;
    const int   i0 = g_idx[base + 0];
    const int   i1 = g_idx[base + 1];
    const int   i2 = g_idx[base + 2];
    const float w0 = g_w[base + 0];
    const float w1 = g_w[base + 1];
    const float w2 = g_w[base + 2];
    const int   qid = g_qid[j];            // original query row

    const float4* f = reinterpret_cast<const float4*>(feat);
    const float4 a = __ldg(f + (size_t)i0 * C4 + cg);
    const float4 b = __ldg(f + (size_t)i1 * C4 + cg);
    const float4 c = __ldg(f + (size_t)i2 * C4 + cg);

    float4 o;
    o.x = fmaf(w2, c.x, fmaf(w1, b.x, w0 * a.x));
    o.y = fmaf(w2, c.y, fmaf(w1, b.y, w0 * a.y));
    o.z = fmaf(w2, c.z, fmaf(w1, b.z, w0 * a.z));
    o.w = fmaf(w2, c.w, fmaf(w1, b.w, w0 * a.w));

    reinterpret_cast<float4*>(out)[(size_t)qid * C4 + cg] = o;
}

extern "C" void kernel_launch(void* const* d_in, const int* in_sizes, int n_in,
                              void* d_out, int out_size)
{
    const float* xyz     = (const float*)d_in[0];
    const float* new_xyz = (const float*)d_in[1];
    const float* feat    = (const float*)d_in[2];

    const int B    = in_sizes[3];
    const int Ntot = in_sizes[0] / 3;
    const int Mtot = in_sizes[1] / 3;
    const int N    = Ntot / B;
    const int M    = Mtot / B;
    const int C    = in_sizes[2] / Ntot;

    const int cells = B * G3;
    zero_kernel<<<(cells + 255) / 256, 256>>>(cells);
    count_kernel<false><<<(Ntot + 255) / 256, 256>>>(xyz, N, Ntot);
    count_kernel<true ><<<(Mtot + 255) / 256, 256>>>(new_xyz, M, Mtot);
    scan_kernel<<<dim3(B, 2), 1024>>>();
    scatter_kernel<false><<<(Ntot + 255) / 256, 256>>>(xyz, N, Ntot);
    scatter_kernel<true ><<<(Mtot + 255) / 256, 256>>>(new_xyz, M, Mtot);

    knn_cell<<<dim3(G3, B), KNN_T>>>(N, M);

    const int C4    = C / 4;
    const int total = Mtot * C4;
    interp_kernel<<<(total + 255) / 256, 256>>>(feat, (float*)d_out, C4, total);
}